// round 16
// baseline (speedup 1.0000x reference)
#include <cuda_runtime.h>
#include <cuda_fp16.h>
#include <cstdint>
#include <math.h>

// Problem constants
#define Bv   2
#define Sv   2048
#define Dv   4096
#define Hv   32
#define KVHv 8
#define HDv  128
#define Mv   (Bv * Sv)       // 4096
#define NQ   (Hv * HDv)      // 4096
#define NKV  (KVHv * HDv)    // 1024
#define NQKV (NQ + 2 * NKV)  // 6144

// fp16 scratch
__device__ __half g_x_hi[(size_t)Mv * Dv];
__device__ __half g_wqkv_hi[(size_t)NQKV * Dv];
__device__ __half g_wo_hi[(size_t)Dv * NQ];
__device__ __half g_at_hi[(size_t)Mv * NQ];
__device__ __half g_qr_hi[(size_t)Mv * NQ];
__device__ __half g_kr_hi[(size_t)Mv * NKV];
__device__ __half g_vs_hi[(size_t)Mv * NKV];

// ---------------------------------------------------------------------------
// Helpers (compute_103-safe)
// ---------------------------------------------------------------------------
__device__ __forceinline__ uint32_t smem_u32(const void* p) {
    uint32_t a;
    asm("{ .reg .u64 t; cvta.to.shared.u64 t, %1; cvt.u32.u64 %0, t; }" : "=r"(a) : "l"(p));
    return a;
}
__device__ __forceinline__ void cp16(uint32_t dst, const void* src) {
    asm volatile("cp.async.cg.shared.global [%0], [%1], 16;" :: "r"(dst), "l"(src));
}
#define CP_COMMIT() asm volatile("cp.async.commit_group;" ::: "memory")
#define CP_WAIT1()  asm volatile("cp.async.wait_group 1;" ::: "memory")
#define CP_WAIT0()  asm volatile("cp.async.wait_group 0;" ::: "memory")

__device__ __forceinline__ void mma_f16(float* c, const uint32_t* a, const uint32_t* b) {
    asm volatile("mma.sync.aligned.m16n8k16.row.col.f32.f16.f16.f32 "
        "{%0,%1,%2,%3}, {%4,%5,%6,%7}, {%8,%9}, {%0,%1,%2,%3};"
        : "+f"(c[0]), "+f"(c[1]), "+f"(c[2]), "+f"(c[3])
        : "r"(a[0]), "r"(a[1]), "r"(a[2]), "r"(a[3]), "r"(b[0]), "r"(b[1]));
}
__device__ __forceinline__ void ldsm_x4(uint32_t* r, uint32_t addr) {
    asm volatile("ldmatrix.sync.aligned.m8n8.x4.shared.b16 {%0,%1,%2,%3}, [%4];"
        : "=r"(r[0]), "=r"(r[1]), "=r"(r[2]), "=r"(r[3]) : "r"(addr));
}
__device__ __forceinline__ void ldsm_x4_t(uint32_t* r, uint32_t addr) {
    asm volatile("ldmatrix.sync.aligned.m8n8.x4.trans.shared.b16 {%0,%1,%2,%3}, [%4];"
        : "=r"(r[0]), "=r"(r[1]), "=r"(r[2]), "=r"(r[3]) : "r"(addr));
}
__device__ __forceinline__ uint32_t pack2h(float x, float y) {
    __half2 t = __floats2half2_rn(x, y);
    return *(uint32_t*)&t;
}

// ---------------------------------------------------------------------------
// fp32 -> fp16, ILP-8 front-batched loads (consecutive indexing, MLP_p1=8).
// All sizes are multiples of 2048 float4s -> full blocks, uniform guards.
// ---------------------------------------------------------------------------
__global__ void cvt_hi(const float* __restrict__ in,
                       __half* __restrict__ hi, long n4) {
    const long base = (long)blockIdx.x * (256 * 8) + threadIdx.x;
    float4 v[8];
#pragma unroll
    for (int j = 0; j < 8; j++) {
        const long idx = base + j * 256;
        if (idx < n4) v[j] = ((const float4*)in)[idx];
    }
#pragma unroll
    for (int j = 0; j < 8; j++) {
        const long idx = base + j * 256;
        if (idx < n4) {
            ((__half2*)hi)[idx * 2]     = __floats2half2_rn(v[j].x, v[j].y);
            ((__half2*)hi)[idx * 2 + 1] = __floats2half2_rn(v[j].z, v[j].w);
        }
    }
}
static inline unsigned cvt_grid(long n4) {
    return (unsigned)((n4 + 2047) / 2048);
}

// ---------------------------------------------------------------------------
// HMMA fp16 1-pass GEMM: C = Ahi @ Bhi^T.  (proven R15)
// 128x128 CTA tile, BK=64, 3-stage pipeline, 96KB smem, 2 CTAs/SM.
// 128B rows with SW128-style chunk swizzle, ldmatrix loads.
// EPI=1: fused RoPE + fp16 epilogue (Q,K: rope; V: plain); EPI=0: fp32 C.
// ---------------------------------------------------------------------------
#define BM 128
#define BN 128
#define BK 64
#define TILE_SM   (128 * 128)         // 16384 B
#define STAGE_SM  (2 * TILE_SM)       // 32768 B (Ahi, Bhi)
#define GEMM_SMEM (3 * STAGE_SM)      // 98304 B
#define SWZ8(r, c8) ((c8) ^ ((r) & 7))

__device__ __forceinline__ void load_stage(
    uint32_t sbase,
    const __half* __restrict__ Ahi, const __half* __restrict__ Bhi,
    int m0, int n0, int k0, int K, int tid)
{
#pragma unroll
    for (int j = 0; j < 8; j++) {
        const int tile = j >> 2;              // 0:Ahi 1:Bhi
        const int cc = tid + (j & 3) * 256;   // 0..1023 within tile
        const int row = cc >> 3;
        const int c8 = cc & 7;
        const uint32_t soff = sbase + tile * TILE_SM + row * 128 + (SWZ8(row, c8) << 4);
        const __half* g = (tile == 0) ? Ahi : Bhi;
        const int grow = (tile == 0) ? (m0 + row) : (n0 + row);
        cp16(soff, g + (size_t)grow * K + k0 + c8 * 8);
    }
}

template <bool EPI>
__global__ __launch_bounds__(256, 2) void gemm_hmma_x1(
    const __half* __restrict__ Ahi, const __half* __restrict__ Bhi,
    float* __restrict__ C,
    __half* __restrict__ Qh, __half* __restrict__ Kh, __half* __restrict__ Vh,
    const float* __restrict__ cs, const float* __restrict__ sn,
    int N, int K)
{
    extern __shared__ char smem[];
    const uint32_t sb = smem_u32(smem);
    const int tid = threadIdx.x;
    const int wid = tid >> 5, lane = tid & 31;
    const int wm = wid & 1;
    const int wn = wid >> 1;
    const int lr = lane >> 2;
    const int m0 = blockIdx.y * BM, n0 = blockIdx.x * BN;

    float acc[4][4][4];
#pragma unroll
    for (int mt = 0; mt < 4; mt++)
#pragma unroll
        for (int nt = 0; nt < 4; nt++)
#pragma unroll
            for (int r = 0; r < 4; r++) acc[mt][nt][r] = 0.f;

    const int NIT = K / BK;

    load_stage(sb,            Ahi, Bhi, m0, n0, 0,  K, tid);
    CP_COMMIT();
    load_stage(sb + STAGE_SM, Ahi, Bhi, m0, n0, BK, K, tid);
    CP_COMMIT();

    const int a_row = lane & 15;
    const int a_chi = lane >> 4;
    const int b_row = (lane & 7) + ((lane >> 4) << 3);
    const int b_chi = (lane >> 3) & 1;

    for (int it = 0; it < NIT; ++it) {
        CP_WAIT1();
        __syncthreads();
        if (it + 2 < NIT)
            load_stage(sb + ((it + 2) % 3) * STAGE_SM,
                       Ahi, Bhi, m0, n0, (it + 2) * BK, K, tid);
        CP_COMMIT();

        const uint32_t sA = sb + (it % 3) * STAGE_SM;
        const uint32_t sB = sA + TILE_SM;
#pragma unroll
        for (int kk = 0; kk < 4; kk++) {
            uint32_t ah[4][4], bh[2][4];
#pragma unroll
            for (int mt = 0; mt < 4; mt++) {
                const int r = wm * 64 + mt * 16 + a_row;
                const int c = kk * 2 + a_chi;
                ldsm_x4(ah[mt], sA + r * 128 + (SWZ8(r, c) << 4));
            }
#pragma unroll
            for (int ntp = 0; ntp < 2; ntp++) {
                const int r = wn * 32 + ntp * 16 + b_row;
                const int c = kk * 2 + b_chi;
                ldsm_x4(bh[ntp], sB + r * 128 + (SWZ8(r, c) << 4));
            }
#pragma unroll
            for (int mt = 0; mt < 4; mt++)
#pragma unroll
                for (int nt = 0; nt < 4; nt++)
                    mma_f16(acc[mt][nt], ah[mt], bh[nt >> 1] + (nt & 1) * 2);
        }
    }

    if (!EPI) {
#pragma unroll
        for (int mt = 0; mt < 4; mt++) {
            const int row = m0 + wm * 64 + mt * 16 + lr;
#pragma unroll
            for (int nt = 0; nt < 4; nt++) {
                const int col = n0 + wn * 32 + nt * 8 + (lane & 3) * 2;
                float2* p0 = (float2*)&C[(size_t)row * N + col];
                float2* p1 = (float2*)&C[(size_t)(row + 8) * N + col];
                *p0 = make_float2(acc[mt][nt][0], acc[mt][nt][1]);
                *p1 = make_float2(acc[mt][nt][2], acc[mt][nt][3]);
            }
        }
    } else {
        __half* Dh;
        int dstride, coff;
        bool dorope;
        if (n0 < NQ)            { Dh = Qh; dstride = NQ;  coff = 0;        dorope = true; }
        else if (n0 < NQ + NKV) { Dh = Kh; dstride = NKV; coff = NQ;       dorope = true; }
        else                    { Dh = Vh; dstride = NKV; coff = NQ + NKV; dorope = false; }
#pragma unroll
        for (int mt = 0; mt < 4; mt++) {
#pragma unroll
            for (int nt = 0; nt < 4; nt++) {
                const int col = n0 + wn * 32 + nt * 8 + (lane & 3) * 2;
                const int fi = (col & 127) >> 1;
#pragma unroll
                for (int r = 0; r < 2; r++) {
                    const int row = m0 + wm * 64 + mt * 16 + lr + 8 * r;
                    float x0 = acc[mt][nt][2 * r];
                    float x1 = acc[mt][nt][2 * r + 1];
                    float y0 = x0, y1 = x1;
                    if (dorope) {
                        const int s = row & (Sv - 1);
                        const float c  = __ldg(cs + s * 64 + fi);
                        const float sv = __ldg(sn + s * 64 + fi);
                        y0 = x0 * c - x1 * sv;
                        y1 = x0 * sv + x1 * c;
                    }
                    *(uint32_t*)&Dh[(size_t)row * dstride + (col - coff)] =
                        pack2h(y0, y1);
                }
            }
        }
    }
}

// ---------------------------------------------------------------------------
// HMMA flash attention, fp16 1-pass (proven R14/R15).
// CTA = 64 q-rows, 128 threads, K/V tiles of 32 rows double-buffered,
// Q register-resident. 51KB smem, 3 CTAs/SM, longest-first order.
// ---------------------------------------------------------------------------
#define FROWB 272
#define FQ_SM    (64 * FROWB)
#define FK_HALF  (32 * FROWB)
#define SM_KV    FQ_SM
#define KV_STAGE (2 * FK_HALF)
#define FLASH_SMEM (SM_KV + 2 * KV_STAGE)   // 52224

__device__ __forceinline__ void flash_load_kv(
    uint32_t sb, int stage,
    const __half* __restrict__ Kh, const __half* __restrict__ Vh,
    size_t gbase, int tid)
{
#pragma unroll
    for (int j = 0; j < 8; j++) {
        const int t = j >> 2;
        const int cc = tid + (j & 3) * 128;
        const int row = cc >> 4, c16 = cc & 15;
        const __half* g = (t == 0) ? Kh : Vh;
        const uint32_t soff = sb + SM_KV + stage * KV_STAGE + t * FK_HALF
                              + row * FROWB + c16 * 16;
        cp16(soff, g + gbase + (size_t)row * NKV + c16 * 8);
    }
}

__global__ __launch_bounds__(128, 3) void flash_hmma(
    const __half* __restrict__ Qh_g,
    const __half* __restrict__ Kh_g, const __half* __restrict__ Vh_g,
    __half* __restrict__ Oh)
{
    extern __shared__ char smem[];
    const uint32_t sb = smem_u32(smem);
    const int tid = threadIdx.x, w = tid >> 5, lane = tid & 31;
    const int lr = lane >> 2, lc = lane & 3;
    const int qb = gridDim.x - 1 - blockIdx.x;   // longest-first
    const int q0 = qb * 64, h = blockIdx.y, b = blockIdx.z;
    const int kvh = h >> 2;
    const float scale = 0.08838834764831845f;

    {
        const size_t gq = ((size_t)(b * Sv + q0)) * NQ + h * HDv;
#pragma unroll
        for (int j = 0; j < 8; j++) {
            const int cc = tid + j * 128;
            const int row = cc >> 4, c16 = cc & 15;
            cp16(sb + row * FROWB + c16 * 16,
                 Qh_g + gq + (size_t)row * NQ + c16 * 8);
        }
    }
    CP_COMMIT();
    flash_load_kv(sb, 0, Kh_g, Vh_g, ((size_t)(b * Sv)) * NKV + kvh * HDv, tid);
    CP_COMMIT();

    const int a_row = lane & 15;
    const int a_cb  = (lane >> 4) << 4;
    const int b_row = (lane & 7) + ((lane >> 4) << 3);
    const int b_cb  = ((lane >> 3) & 1) << 4;

    CP_WAIT1();
    __syncthreads();
    uint32_t qh[8][4];
#pragma unroll
    for (int kf = 0; kf < 8; kf++)
        ldsm_x4(qh[kf], sb + (w * 16 + a_row) * FROWB + kf * 32 + a_cb);

    float o[16][4];
#pragma unroll
    for (int i = 0; i < 16; i++)
#pragma unroll
        for (int j = 0; j < 4; j++) o[i][j] = 0.f;
    float mrow[2] = {-1e30f, -1e30f};
    float lrow[2] = {0.f, 0.f};

    const int ktmax = 2 * qb + 1;
    for (int kt = 0; kt <= ktmax; ++kt) {
        CP_WAIT0();
        __syncthreads();
        if (kt < ktmax) {
            flash_load_kv(sb, (kt + 1) & 1, Kh_g, Vh_g,
                          ((size_t)(b * Sv + (kt + 1) * 32)) * NKV + kvh * HDv, tid);
            CP_COMMIT();
        }

        const int k0 = kt * 32;
        if (k0 > q0 + w * 16 + 15) continue;

        const uint32_t Kst = sb + SM_KV + (kt & 1) * KV_STAGE;
        const uint32_t Vst = Kst + FK_HALF;

        float s[4][4];
#pragma unroll
        for (int nf = 0; nf < 4; nf++)
#pragma unroll
            for (int r = 0; r < 4; r++) s[nf][r] = 0.f;

#pragma unroll
        for (int kf = 0; kf < 8; kf++) {
#pragma unroll
            for (int nfp = 0; nfp < 2; nfp++) {
                const uint32_t kaddr = Kst + (nfp * 16 + b_row) * FROWB + kf * 32 + b_cb;
                uint32_t bh4[4];
                ldsm_x4(bh4, kaddr);
                mma_f16(s[2 * nfp],     qh[kf], bh4);
                mma_f16(s[2 * nfp + 1], qh[kf], bh4 + 2);
            }
        }

        const bool diag = (k0 + 31 > q0 + w * 16);
#pragma unroll
        for (int r = 0; r < 2; r++) {
            const int qrow = q0 + w * 16 + lr + 8 * r;
            float mx = -1e30f;
#pragma unroll
            for (int nf = 0; nf < 4; nf++) {
                float v0 = s[nf][2 * r] * scale;
                float v1 = s[nf][2 * r + 1] * scale;
                if (diag) {
                    const int col = k0 + nf * 8 + lc * 2;
                    if (col > qrow) v0 = -1e30f;
                    if (col + 1 > qrow) v1 = -1e30f;
                }
                s[nf][2 * r] = v0;
                s[nf][2 * r + 1] = v1;
                mx = fmaxf(mx, fmaxf(v0, v1));
            }
            mx = fmaxf(mx, __shfl_xor_sync(0xffffffffu, mx, 1));
            mx = fmaxf(mx, __shfl_xor_sync(0xffffffffu, mx, 2));
            const float m_new = fmaxf(mrow[r], mx);
            const float alpha = __expf(mrow[r] - m_new);
            mrow[r] = m_new;
            float sum = 0.f;
#pragma unroll
            for (int nf = 0; nf < 4; nf++) {
                float p0 = __expf(s[nf][2 * r] - m_new);
                float p1 = __expf(s[nf][2 * r + 1] - m_new);
                s[nf][2 * r] = p0;
                s[nf][2 * r + 1] = p1;
                sum += p0 + p1;
            }
            sum += __shfl_xor_sync(0xffffffffu, sum, 1);
            sum += __shfl_xor_sync(0xffffffffu, sum, 2);
            lrow[r] = lrow[r] * alpha + sum;
#pragma unroll
            for (int nf2 = 0; nf2 < 16; nf2++) {
                o[nf2][2 * r] *= alpha;
                o[nf2][2 * r + 1] *= alpha;
            }
        }

        uint32_t phi[2][4];
#pragma unroll
        for (int kf2 = 0; kf2 < 2; kf2++) {
#pragma unroll
            for (int m = 0; m < 2; m++) {
                const int nf = 2 * kf2 + m;
                phi[kf2][2 * m]     = pack2h(s[nf][0], s[nf][1]);
                phi[kf2][2 * m + 1] = pack2h(s[nf][2], s[nf][3]);
            }
        }

#pragma unroll
        for (int kf2 = 0; kf2 < 2; kf2++) {
#pragma unroll
            for (int nfp = 0; nfp < 8; nfp++) {
                const uint32_t va = Vst + (kf2 * 16 + (lane & 15)) * FROWB
                                    + (nfp * 16 + ((lane >> 4) << 3)) * 2;
                uint32_t bh4[4];
                ldsm_x4_t(bh4, va);
                mma_f16(o[2 * nfp],     phi[kf2], bh4);
                mma_f16(o[2 * nfp + 1], phi[kf2], bh4 + 2);
            }
        }
    }

#pragma unroll
    for (int r = 0; r < 2; r++) {
        const float inv = 1.f / lrow[r];
        const int row = q0 + w * 16 + lr + 8 * r;
        const size_t base = ((size_t)(b * Sv + row)) * NQ + h * HDv + lc * 2;
#pragma unroll
        for (int nf2 = 0; nf2 < 16; nf2++) {
            *(uint32_t*)&Oh[base + nf2 * 8] =
                pack2h(o[nf2][2 * r] * inv, o[nf2][2 * r + 1] * inv);
        }
    }
}

// ---------------------------------------------------------------------------
// Launch. Inputs: 0=x 1=cos 2=sin 3=positions 4=mask 5=wq 6=wk 7=wv 8=wo
// ---------------------------------------------------------------------------
extern "C" void kernel_launch(void* const* d_in, const int* in_sizes, int n_in,
                              void* d_out, int out_size)
{
    const float* x  = (const float*)d_in[0];
    const float* fc = (const float*)d_in[1];
    const float* fs = (const float*)d_in[2];
    const float* wq = (const float*)d_in[5];
    const float* wk = (const float*)d_in[6];
    const float* wv = (const float*)d_in[7];
    const float* wo = (const float*)d_in[8];
    float* out = (float*)d_out;

    __half *xh, *wh, *oh, *ah, *qrh, *krh, *vsh;
    cudaGetSymbolAddress((void**)&xh, g_x_hi);
    cudaGetSymbolAddress((void**)&wh, g_wqkv_hi);
    cudaGetSymbolAddress((void**)&oh, g_wo_hi);
    cudaGetSymbolAddress((void**)&ah, g_at_hi);
    cudaGetSymbolAddress((void**)&qrh, g_qr_hi);
    cudaGetSymbolAddress((void**)&krh, g_kr_hi);
    cudaGetSymbolAddress((void**)&vsh, g_vs_hi);

    // conversions: everything -> fp16 (concatenated wqkv), ILP-8 batched
    {
        long n4;
        n4 = (long)Mv * Dv / 4;
        cvt_hi<<<cvt_grid(n4), 256>>>(x, xh, n4);
        n4 = (long)NQ * Dv / 4;
        cvt_hi<<<cvt_grid(n4), 256>>>(wq, wh, n4);
        n4 = (long)NKV * Dv / 4;
        cvt_hi<<<cvt_grid(n4), 256>>>(wk, wh + (size_t)NQ * Dv, n4);
        cvt_hi<<<cvt_grid(n4), 256>>>(wv, wh + (size_t)(NQ + NKV) * Dv, n4);
        n4 = (long)Dv * NQ / 4;
        cvt_hi<<<cvt_grid(n4), 256>>>(wo, oh, n4);
    }

    cudaFuncSetAttribute(gemm_hmma_x1<true>,
                         cudaFuncAttributeMaxDynamicSharedMemorySize, GEMM_SMEM);
    cudaFuncSetAttribute(gemm_hmma_x1<false>,
                         cudaFuncAttributeMaxDynamicSharedMemorySize, GEMM_SMEM);

    // Fused QKV projection + RoPE (1-pass, BK=64)
    gemm_hmma_x1<true><<<dim3(NQKV / BN, Mv / BM), 256, GEMM_SMEM>>>(
        xh, wh, nullptr,
        qrh, krh, vsh, fc, fs, NQKV, Dv);

    // Flash attention (fp16 1-pass, 3 CTAs/SM, longest-first)
    cudaFuncSetAttribute(flash_hmma, cudaFuncAttributeMaxDynamicSharedMemorySize, FLASH_SMEM);
    flash_hmma<<<dim3(Sv / 64, Hv, Bv), 128, FLASH_SMEM>>>(
        qrh, krh, vsh, ah);

    // Output projection (1-pass, BK=64)
    gemm_hmma_x1<false><<<dim3(NQ / BN, Mv / BM), 256, GEMM_SMEM>>>(
        ah, oh, out,
        nullptr, nullptr, nullptr, nullptr, nullptr, NQ, Dv);
}

// round 17
// speedup vs baseline: 1.0482x; 1.0482x over previous
#include <cuda_runtime.h>
#include <cuda_fp16.h>
#include <cstdint>
#include <math.h>

// Problem constants
#define Bv   2
#define Sv   2048
#define Dv   4096
#define Hv   32
#define KVHv 8
#define HDv  128
#define Mv   (Bv * Sv)       // 4096
#define NQ   (Hv * HDv)      // 4096
#define NKV  (KVHv * HDv)    // 1024
#define NQKV (NQ + 2 * NKV)  // 6144

// fp16 scratch
__device__ __half g_x_hi[(size_t)Mv * Dv];
__device__ __half g_wqkv_hi[(size_t)NQKV * Dv];
__device__ __half g_wo_hi[(size_t)Dv * NQ];
__device__ __half g_at_hi[(size_t)Mv * NQ];
__device__ __half g_qr_hi[(size_t)Mv * NQ];
__device__ __half g_kr_hi[(size_t)Mv * NKV];
__device__ __half g_vs_hi[(size_t)Mv * NKV];

// ---------------------------------------------------------------------------
// Helpers (compute_103-safe)
// ---------------------------------------------------------------------------
__device__ __forceinline__ uint32_t smem_u32(const void* p) {
    uint32_t a;
    asm("{ .reg .u64 t; cvta.to.shared.u64 t, %1; cvt.u32.u64 %0, t; }" : "=r"(a) : "l"(p));
    return a;
}
__device__ __forceinline__ void cp16(uint32_t dst, const void* src) {
    asm volatile("cp.async.cg.shared.global [%0], [%1], 16;" :: "r"(dst), "l"(src));
}
#define CP_COMMIT() asm volatile("cp.async.commit_group;" ::: "memory")
#define CP_WAIT1()  asm volatile("cp.async.wait_group 1;" ::: "memory")
#define CP_WAIT0()  asm volatile("cp.async.wait_group 0;" ::: "memory")

__device__ __forceinline__ void mma_f16(float* c, const uint32_t* a, const uint32_t* b) {
    asm volatile("mma.sync.aligned.m16n8k16.row.col.f32.f16.f16.f32 "
        "{%0,%1,%2,%3}, {%4,%5,%6,%7}, {%8,%9}, {%0,%1,%2,%3};"
        : "+f"(c[0]), "+f"(c[1]), "+f"(c[2]), "+f"(c[3])
        : "r"(a[0]), "r"(a[1]), "r"(a[2]), "r"(a[3]), "r"(b[0]), "r"(b[1]));
}
__device__ __forceinline__ void ldsm_x4(uint32_t* r, uint32_t addr) {
    asm volatile("ldmatrix.sync.aligned.m8n8.x4.shared.b16 {%0,%1,%2,%3}, [%4];"
        : "=r"(r[0]), "=r"(r[1]), "=r"(r[2]), "=r"(r[3]) : "r"(addr));
}
__device__ __forceinline__ void ldsm_x4_t(uint32_t* r, uint32_t addr) {
    asm volatile("ldmatrix.sync.aligned.m8n8.x4.trans.shared.b16 {%0,%1,%2,%3}, [%4];"
        : "=r"(r[0]), "=r"(r[1]), "=r"(r[2]), "=r"(r[3]) : "r"(addr));
}
__device__ __forceinline__ uint32_t pack2h(float x, float y) {
    __half2 t = __floats2half2_rn(x, y);
    return *(uint32_t*)&t;
}

// ---------------------------------------------------------------------------
// Fused fp32 -> fp16 conversion: all 5 tensors in ONE launch.
// Segments (in 2048-float4 blocks): x:2048, wq:2048, wk:512, wv:512, wo:2048.
// ---------------------------------------------------------------------------
#define CVT_BLK_X   2048
#define CVT_BLK_WQ  2048
#define CVT_BLK_WK  512
#define CVT_BLK_WV  512
#define CVT_BLK_WO  2048
#define CVT_GRID (CVT_BLK_X + CVT_BLK_WQ + CVT_BLK_WK + CVT_BLK_WV + CVT_BLK_WO)

__global__ void cvt_all(const float* __restrict__ x,  const float* __restrict__ wq,
                        const float* __restrict__ wk, const float* __restrict__ wv,
                        const float* __restrict__ wo,
                        __half* __restrict__ xh, __half* __restrict__ wh,
                        __half* __restrict__ oh)
{
    int blk = blockIdx.x;
    const float* src;
    __half* dst;
    if (blk < CVT_BLK_X)                       { src = x;  dst = xh; }
    else if ((blk -= CVT_BLK_X) < CVT_BLK_WQ)  { src = wq; dst = wh; }
    else if ((blk -= CVT_BLK_WQ) < CVT_BLK_WK) { src = wk; dst = wh + (size_t)NQ * Dv; }
    else if ((blk -= CVT_BLK_WK) < CVT_BLK_WV) { src = wv; dst = wh + (size_t)(NQ + NKV) * Dv; }
    else { blk -= CVT_BLK_WV;                    src = wo; dst = oh; }

    const long base = (long)blk * (256 * 8) + threadIdx.x;
    float4 v[8];
#pragma unroll
    for (int j = 0; j < 8; j++) v[j] = ((const float4*)src)[base + j * 256];
#pragma unroll
    for (int j = 0; j < 8; j++) {
        const long idx = base + j * 256;
        ((__half2*)dst)[idx * 2]     = __floats2half2_rn(v[j].x, v[j].y);
        ((__half2*)dst)[idx * 2 + 1] = __floats2half2_rn(v[j].z, v[j].w);
    }
}

// ---------------------------------------------------------------------------
// HMMA fp16 1-pass GEMM: C = Ahi @ Bhi^T.  (proven R15/R16)
// 128x128 CTA tile, BK=64, 3-stage pipeline, 96KB smem, 2 CTAs/SM.
// ---------------------------------------------------------------------------
#define BM 128
#define BN 128
#define BK 64
#define TILE_SM   (128 * 128)
#define STAGE_SM  (2 * TILE_SM)
#define GEMM_SMEM (3 * STAGE_SM)
#define SWZ8(r, c8) ((c8) ^ ((r) & 7))

__device__ __forceinline__ void load_stage(
    uint32_t sbase,
    const __half* __restrict__ Ahi, const __half* __restrict__ Bhi,
    int m0, int n0, int k0, int K, int tid)
{
#pragma unroll
    for (int j = 0; j < 8; j++) {
        const int tile = j >> 2;
        const int cc = tid + (j & 3) * 256;
        const int row = cc >> 3;
        const int c8 = cc & 7;
        const uint32_t soff = sbase + tile * TILE_SM + row * 128 + (SWZ8(row, c8) << 4);
        const __half* g = (tile == 0) ? Ahi : Bhi;
        const int grow = (tile == 0) ? (m0 + row) : (n0 + row);
        cp16(soff, g + (size_t)grow * K + k0 + c8 * 8);
    }
}

template <bool EPI>
__global__ __launch_bounds__(256, 2) void gemm_hmma_x1(
    const __half* __restrict__ Ahi, const __half* __restrict__ Bhi,
    float* __restrict__ C,
    __half* __restrict__ Qh, __half* __restrict__ Kh, __half* __restrict__ Vh,
    const float* __restrict__ cs, const float* __restrict__ sn,
    int N, int K)
{
    extern __shared__ char smem[];
    const uint32_t sb = smem_u32(smem);
    const int tid = threadIdx.x;
    const int wid = tid >> 5, lane = tid & 31;
    const int wm = wid & 1;
    const int wn = wid >> 1;
    const int lr = lane >> 2;
    const int m0 = blockIdx.y * BM, n0 = blockIdx.x * BN;

    float acc[4][4][4];
#pragma unroll
    for (int mt = 0; mt < 4; mt++)
#pragma unroll
        for (int nt = 0; nt < 4; nt++)
#pragma unroll
            for (int r = 0; r < 4; r++) acc[mt][nt][r] = 0.f;

    const int NIT = K / BK;

    load_stage(sb,            Ahi, Bhi, m0, n0, 0,  K, tid);
    CP_COMMIT();
    load_stage(sb + STAGE_SM, Ahi, Bhi, m0, n0, BK, K, tid);
    CP_COMMIT();

    const int a_row = lane & 15;
    const int a_chi = lane >> 4;
    const int b_row = (lane & 7) + ((lane >> 4) << 3);
    const int b_chi = (lane >> 3) & 1;

    for (int it = 0; it < NIT; ++it) {
        CP_WAIT1();
        __syncthreads();
        if (it + 2 < NIT)
            load_stage(sb + ((it + 2) % 3) * STAGE_SM,
                       Ahi, Bhi, m0, n0, (it + 2) * BK, K, tid);
        CP_COMMIT();

        const uint32_t sA = sb + (it % 3) * STAGE_SM;
        const uint32_t sB = sA + TILE_SM;
#pragma unroll
        for (int kk = 0; kk < 4; kk++) {
            uint32_t ah[4][4], bh[2][4];
#pragma unroll
            for (int mt = 0; mt < 4; mt++) {
                const int r = wm * 64 + mt * 16 + a_row;
                const int c = kk * 2 + a_chi;
                ldsm_x4(ah[mt], sA + r * 128 + (SWZ8(r, c) << 4));
            }
#pragma unroll
            for (int ntp = 0; ntp < 2; ntp++) {
                const int r = wn * 32 + ntp * 16 + b_row;
                const int c = kk * 2 + b_chi;
                ldsm_x4(bh[ntp], sB + r * 128 + (SWZ8(r, c) << 4));
            }
#pragma unroll
            for (int mt = 0; mt < 4; mt++)
#pragma unroll
                for (int nt = 0; nt < 4; nt++)
                    mma_f16(acc[mt][nt], ah[mt], bh[nt >> 1] + (nt & 1) * 2);
        }
    }

    if (!EPI) {
#pragma unroll
        for (int mt = 0; mt < 4; mt++) {
            const int row = m0 + wm * 64 + mt * 16 + lr;
#pragma unroll
            for (int nt = 0; nt < 4; nt++) {
                const int col = n0 + wn * 32 + nt * 8 + (lane & 3) * 2;
                float2* p0 = (float2*)&C[(size_t)row * N + col];
                float2* p1 = (float2*)&C[(size_t)(row + 8) * N + col];
                *p0 = make_float2(acc[mt][nt][0], acc[mt][nt][1]);
                *p1 = make_float2(acc[mt][nt][2], acc[mt][nt][3]);
            }
        }
    } else {
        __half* Dh;
        int dstride, coff;
        bool dorope;
        if (n0 < NQ)            { Dh = Qh; dstride = NQ;  coff = 0;        dorope = true; }
        else if (n0 < NQ + NKV) { Dh = Kh; dstride = NKV; coff = NQ;       dorope = true; }
        else                    { Dh = Vh; dstride = NKV; coff = NQ + NKV; dorope = false; }
#pragma unroll
        for (int mt = 0; mt < 4; mt++) {
#pragma unroll
            for (int nt = 0; nt < 4; nt++) {
                const int col = n0 + wn * 32 + nt * 8 + (lane & 3) * 2;
                const int fi = (col & 127) >> 1;
#pragma unroll
                for (int r = 0; r < 2; r++) {
                    const int row = m0 + wm * 64 + mt * 16 + lr + 8 * r;
                    float x0 = acc[mt][nt][2 * r];
                    float x1 = acc[mt][nt][2 * r + 1];
                    float y0 = x0, y1 = x1;
                    if (dorope) {
                        const int s = row & (Sv - 1);
                        const float c  = __ldg(cs + s * 64 + fi);
                        const float sv = __ldg(sn + s * 64 + fi);
                        y0 = x0 * c - x1 * sv;
                        y1 = x0 * sv + x1 * c;
                    }
                    *(uint32_t*)&Dh[(size_t)row * dstride + (col - coff)] =
                        pack2h(y0, y1);
                }
            }
        }
    }
}

// ---------------------------------------------------------------------------
// HMMA flash attention, fp16 1-pass (proven), 1D grid with GLOBAL
// longest-first ordering: id -> qb = 31 - id/64 (all longest CTAs first,
// final wave holds only the shortest).
// CTA = 64 q-rows, 128 threads, K/V tiles of 32 rows double-buffered,
// Q register-resident. 51KB smem, 3 CTAs/SM.
// ---------------------------------------------------------------------------
#define FROWB 272
#define FQ_SM    (64 * FROWB)
#define FK_HALF  (32 * FROWB)
#define SM_KV    FQ_SM
#define KV_STAGE (2 * FK_HALF)
#define FLASH_SMEM (SM_KV + 2 * KV_STAGE)   // 52224

__device__ __forceinline__ void flash_load_kv(
    uint32_t sb, int stage,
    const __half* __restrict__ Kh, const __half* __restrict__ Vh,
    size_t gbase, int tid)
{
#pragma unroll
    for (int j = 0; j < 8; j++) {
        const int t = j >> 2;
        const int cc = tid + (j & 3) * 128;
        const int row = cc >> 4, c16 = cc & 15;
        const __half* g = (t == 0) ? Kh : Vh;
        const uint32_t soff = sb + SM_KV + stage * KV_STAGE + t * FK_HALF
                              + row * FROWB + c16 * 16;
        cp16(soff, g + gbase + (size_t)row * NKV + c16 * 8);
    }
}

__global__ __launch_bounds__(128, 3) void flash_hmma(
    const __half* __restrict__ Qh_g,
    const __half* __restrict__ Kh_g, const __half* __restrict__ Vh_g,
    __half* __restrict__ Oh)
{
    extern __shared__ char smem[];
    const uint32_t sb = smem_u32(smem);
    const int tid = threadIdx.x, w = tid >> 5, lane = tid & 31;
    const int lr = lane >> 2, lc = lane & 3;
    // global longest-first decode
    const int id = blockIdx.x;
    const int qb = (Sv / 64 - 1) - (id >> 6);    // 31..0, longest first
    const int rem = id & 63;
    const int h = rem & 31;
    const int b = rem >> 5;
    const int q0 = qb * 64;
    const int kvh = h >> 2;
    const float scale = 0.08838834764831845f;

    {
        const size_t gq = ((size_t)(b * Sv + q0)) * NQ + h * HDv;
#pragma unroll
        for (int j = 0; j < 8; j++) {
            const int cc = tid + j * 128;
            const int row = cc >> 4, c16 = cc & 15;
            cp16(sb + row * FROWB + c16 * 16,
                 Qh_g + gq + (size_t)row * NQ + c16 * 8);
        }
    }
    CP_COMMIT();
    flash_load_kv(sb, 0, Kh_g, Vh_g, ((size_t)(b * Sv)) * NKV + kvh * HDv, tid);
    CP_COMMIT();

    const int a_row = lane & 15;
    const int a_cb  = (lane >> 4) << 4;
    const int b_row = (lane & 7) + ((lane >> 4) << 3);
    const int b_cb  = ((lane >> 3) & 1) << 4;

    CP_WAIT1();
    __syncthreads();
    uint32_t qh[8][4];
#pragma unroll
    for (int kf = 0; kf < 8; kf++)
        ldsm_x4(qh[kf], sb + (w * 16 + a_row) * FROWB + kf * 32 + a_cb);

    float o[16][4];
#pragma unroll
    for (int i = 0; i < 16; i++)
#pragma unroll
        for (int j = 0; j < 4; j++) o[i][j] = 0.f;
    float mrow[2] = {-1e30f, -1e30f};
    float lrow[2] = {0.f, 0.f};

    const int ktmax = 2 * qb + 1;
    for (int kt = 0; kt <= ktmax; ++kt) {
        CP_WAIT0();
        __syncthreads();
        if (kt < ktmax) {
            flash_load_kv(sb, (kt + 1) & 1, Kh_g, Vh_g,
                          ((size_t)(b * Sv + (kt + 1) * 32)) * NKV + kvh * HDv, tid);
            CP_COMMIT();
        }

        const int k0 = kt * 32;
        if (k0 > q0 + w * 16 + 15) continue;

        const uint32_t Kst = sb + SM_KV + (kt & 1) * KV_STAGE;
        const uint32_t Vst = Kst + FK_HALF;

        float s[4][4];
#pragma unroll
        for (int nf = 0; nf < 4; nf++)
#pragma unroll
            for (int r = 0; r < 4; r++) s[nf][r] = 0.f;

#pragma unroll
        for (int kf = 0; kf < 8; kf++) {
#pragma unroll
            for (int nfp = 0; nfp < 2; nfp++) {
                const uint32_t kaddr = Kst + (nfp * 16 + b_row) * FROWB + kf * 32 + b_cb;
                uint32_t bh4[4];
                ldsm_x4(bh4, kaddr);
                mma_f16(s[2 * nfp],     qh[kf], bh4);
                mma_f16(s[2 * nfp + 1], qh[kf], bh4 + 2);
            }
        }

        const bool diag = (k0 + 31 > q0 + w * 16);
#pragma unroll
        for (int r = 0; r < 2; r++) {
            const int qrow = q0 + w * 16 + lr + 8 * r;
            float mx = -1e30f;
#pragma unroll
            for (int nf = 0; nf < 4; nf++) {
                float v0 = s[nf][2 * r] * scale;
                float v1 = s[nf][2 * r + 1] * scale;
                if (diag) {
                    const int col = k0 + nf * 8 + lc * 2;
                    if (col > qrow) v0 = -1e30f;
                    if (col + 1 > qrow) v1 = -1e30f;
                }
                s[nf][2 * r] = v0;
                s[nf][2 * r + 1] = v1;
                mx = fmaxf(mx, fmaxf(v0, v1));
            }
            mx = fmaxf(mx, __shfl_xor_sync(0xffffffffu, mx, 1));
            mx = fmaxf(mx, __shfl_xor_sync(0xffffffffu, mx, 2));
            const float m_new = fmaxf(mrow[r], mx);
            const float alpha = __expf(mrow[r] - m_new);
            mrow[r] = m_new;
            float sum = 0.f;
#pragma unroll
            for (int nf = 0; nf < 4; nf++) {
                float p0 = __expf(s[nf][2 * r] - m_new);
                float p1 = __expf(s[nf][2 * r + 1] - m_new);
                s[nf][2 * r] = p0;
                s[nf][2 * r + 1] = p1;
                sum += p0 + p1;
            }
            sum += __shfl_xor_sync(0xffffffffu, sum, 1);
            sum += __shfl_xor_sync(0xffffffffu, sum, 2);
            lrow[r] = lrow[r] * alpha + sum;
#pragma unroll
            for (int nf2 = 0; nf2 < 16; nf2++) {
                o[nf2][2 * r] *= alpha;
                o[nf2][2 * r + 1] *= alpha;
            }
        }

        uint32_t phi[2][4];
#pragma unroll
        for (int kf2 = 0; kf2 < 2; kf2++) {
#pragma unroll
            for (int m = 0; m < 2; m++) {
                const int nf = 2 * kf2 + m;
                phi[kf2][2 * m]     = pack2h(s[nf][0], s[nf][1]);
                phi[kf2][2 * m + 1] = pack2h(s[nf][2], s[nf][3]);
            }
        }

#pragma unroll
        for (int kf2 = 0; kf2 < 2; kf2++) {
#pragma unroll
            for (int nfp = 0; nfp < 8; nfp++) {
                const uint32_t va = Vst + (kf2 * 16 + (lane & 15)) * FROWB
                                    + (nfp * 16 + ((lane >> 4) << 3)) * 2;
                uint32_t bh4[4];
                ldsm_x4_t(bh4, va);
                mma_f16(o[2 * nfp],     phi[kf2], bh4);
                mma_f16(o[2 * nfp + 1], phi[kf2], bh4 + 2);
            }
        }
    }

#pragma unroll
    for (int r = 0; r < 2; r++) {
        const float inv = 1.f / lrow[r];
        const int row = q0 + w * 16 + lr + 8 * r;
        const size_t base = ((size_t)(b * Sv + row)) * NQ + h * HDv + lc * 2;
#pragma unroll
        for (int nf2 = 0; nf2 < 16; nf2++) {
            *(uint32_t*)&Oh[base + nf2 * 8] =
                pack2h(o[nf2][2 * r] * inv, o[nf2][2 * r + 1] * inv);
        }
    }
}

// ---------------------------------------------------------------------------
// Launch. Inputs: 0=x 1=cos 2=sin 3=positions 4=mask 5=wq 6=wk 7=wv 8=wo
// ---------------------------------------------------------------------------
extern "C" void kernel_launch(void* const* d_in, const int* in_sizes, int n_in,
                              void* d_out, int out_size)
{
    const float* x  = (const float*)d_in[0];
    const float* fc = (const float*)d_in[1];
    const float* fs = (const float*)d_in[2];
    const float* wq = (const float*)d_in[5];
    const float* wk = (const float*)d_in[6];
    const float* wv = (const float*)d_in[7];
    const float* wo = (const float*)d_in[8];
    float* out = (float*)d_out;

    __half *xh, *wh, *oh, *ah, *qrh, *krh, *vsh;
    cudaGetSymbolAddress((void**)&xh, g_x_hi);
    cudaGetSymbolAddress((void**)&wh, g_wqkv_hi);
    cudaGetSymbolAddress((void**)&oh, g_wo_hi);
    cudaGetSymbolAddress((void**)&ah, g_at_hi);
    cudaGetSymbolAddress((void**)&qrh, g_qr_hi);
    cudaGetSymbolAddress((void**)&krh, g_kr_hi);
    cudaGetSymbolAddress((void**)&vsh, g_vs_hi);

    // fused conversion: all 5 tensors, one launch
    cvt_all<<<CVT_GRID, 256>>>(x, wq, wk, wv, wo, xh, wh, oh);

    cudaFuncSetAttribute(gemm_hmma_x1<true>,
                         cudaFuncAttributeMaxDynamicSharedMemorySize, GEMM_SMEM);
    cudaFuncSetAttribute(gemm_hmma_x1<false>,
                         cudaFuncAttributeMaxDynamicSharedMemorySize, GEMM_SMEM);

    // Fused QKV projection + RoPE (1-pass, BK=64)
    gemm_hmma_x1<true><<<dim3(NQKV / BN, Mv / BM), 256, GEMM_SMEM>>>(
        xh, wh, nullptr,
        qrh, krh, vsh, fc, fs, NQKV, Dv);

    // Flash attention (fp16 1-pass, 3 CTAs/SM, global longest-first)
    cudaFuncSetAttribute(flash_hmma, cudaFuncAttributeMaxDynamicSharedMemorySize, FLASH_SMEM);
    flash_hmma<<<(Sv / 64) * Hv * Bv, 128, FLASH_SMEM>>>(
        qrh, krh, vsh, ah);

    // Output projection (1-pass, BK=64)
    gemm_hmma_x1<false><<<dim3(NQ / BN, Mv / BM), 256, GEMM_SMEM>>>(
        ah, oh, out,
        nullptr, nullptr, nullptr, nullptr, nullptr, NQ, Dv);
}